// round 8
// baseline (speedup 1.0000x reference)
#include <cuda_runtime.h>
#include <cstdint>

#define BTOK 4096
#define DDIM 2048
#define HDIM 2048
#define NEXP 8

// ---------------- static device scratch (allocations are forbidden) ----------
__device__ int   g_cnt[NEXP];
__device__ int   g_tok[NEXP][BTOK];
__device__ float g_w[NEXP][BTOK];
__device__ int   g_ticket;
__device__ int   g_ntile;
__device__ int   g_tiles[NEXP * 32 * 16];             // packed (e<<9)|(mt<<4)|nt
__device__ float g_xr[(size_t)BTOK * DDIM];           // rna(x)   (GEMM A source)
__device__ float g_wr[(size_t)NEXP * DDIM * HDIM];    // rna(We)  (GEMM B source)

// ---------------- helpers ----------------------------------------------------
__device__ __forceinline__ uint32_t smem_u32(const void* p) {
    uint32_t a;
    asm("{ .reg .u64 t; cvta.to.shared.u64 t, %1; cvt.u32.u64 %0, t; }" : "=r"(a) : "l"(p));
    return a;
}
__device__ __forceinline__ float f2tf32f(float f) {
    uint32_t r; asm("cvt.rna.tf32.f32 %0, %1;" : "=r"(r) : "f"(f));
    return __uint_as_float(r);
}
#define CPA16(dst, src) \
    asm volatile("cp.async.cg.shared.global [%0], [%1], 16;" :: "r"(dst), "l"(src) : "memory")
#define CPA_COMMIT() asm volatile("cp.async.commit_group;" ::: "memory")
#define CPA_WAIT1()  asm volatile("cp.async.wait_group 1;" ::: "memory")
#define CPA_WAIT0()  asm volatile("cp.async.wait_group 0;" ::: "memory")

__device__ __forceinline__ void mma_tf32(float* c, const uint32_t* a, const uint32_t* b) {
    asm volatile(
        "mma.sync.aligned.m16n8k8.row.col.f32.tf32.tf32.f32 "
        "{%0,%1,%2,%3}, {%4,%5,%6,%7}, {%8,%9}, {%0,%1,%2,%3};"
        : "+f"(c[0]), "+f"(c[1]), "+f"(c[2]), "+f"(c[3])
        : "r"(a[0]), "r"(a[1]), "r"(a[2]), "r"(a[3]), "r"(b[0]), "r"(b[1]));
}

// ---------------- zero output + counters -------------------------------------
__global__ void k_zero(float4* __restrict__ out4) {
    long i = (long)blockIdx.x * blockDim.x + threadIdx.x;
    out4[i] = make_float4(0.f, 0.f, 0.f, 0.f);
    if (blockIdx.x == 0 && threadIdx.x < NEXP) g_cnt[threadIdx.x] = 0;
}

// ---------------- pre-round inputs to tf32 (rna) ------------------------------
__global__ void k_round(const float4* __restrict__ src, float4* __restrict__ dst, int n4) {
    int i = blockIdx.x * blockDim.x + threadIdx.x;
    if (i < n4) {
        float4 v = src[i];
        v.x = f2tf32f(v.x); v.y = f2tf32f(v.y);
        v.z = f2tf32f(v.z); v.w = f2tf32f(v.w);
        dst[i] = v;
    }
}

// ---------------- gating: softmax + top-2 routing (original x) ----------------
__global__ void k_gate(const float* __restrict__ x,
                       const float* __restrict__ Wg,
                       const float* __restrict__ bg) {
    int b    = blockIdx.x * 8 + threadIdx.y;
    int lane = threadIdx.x;
    const float* xr = x + (size_t)b * DDIM;
    float acc[NEXP];
#pragma unroll
    for (int e = 0; e < NEXP; e++) acc[e] = 0.f;
    for (int c = lane; c < DDIM; c += 32) {
        float xv = xr[c];
        const float4* w4 = reinterpret_cast<const float4*>(Wg + (size_t)c * NEXP);
        float4 w0 = w4[0], w1 = w4[1];
        acc[0] += xv * w0.x;  acc[1] += xv * w0.y;
        acc[2] += xv * w0.z;  acc[3] += xv * w0.w;
        acc[4] += xv * w1.x;  acc[5] += xv * w1.y;
        acc[6] += xv * w1.z;  acc[7] += xv * w1.w;
    }
#pragma unroll
    for (int off = 16; off > 0; off >>= 1)
#pragma unroll
        for (int e = 0; e < NEXP; e++)
            acc[e] += __shfl_xor_sync(0xFFFFFFFFu, acc[e], off);

    if (lane == 0) {
        float lg[NEXP], p[NEXP];
        float mx = -1e30f;
#pragma unroll
        for (int e = 0; e < NEXP; e++) { lg[e] = acc[e] + bg[e]; mx = fmaxf(mx, lg[e]); }
        float s = 0.f;
#pragma unroll
        for (int e = 0; e < NEXP; e++) { p[e] = expf(lg[e] - mx); s += p[e]; }
        float inv = 1.f / s;
        int i1 = 0;
#pragma unroll
        for (int e = 1; e < NEXP; e++) if (lg[e] > lg[i1]) i1 = e;
        int i2 = -1;
#pragma unroll
        for (int e = 0; e < NEXP; e++)
            if (e != i1 && (i2 < 0 || lg[e] > lg[i2])) i2 = e;
        int p1 = atomicAdd(&g_cnt[i1], 1);
        g_tok[i1][p1] = b;  g_w[i1][p1] = p[i1] * inv;
        int p2 = atomicAdd(&g_cnt[i2], 1);
        g_tok[i2][p2] = b;  g_w[i2][p2] = p[i2] * inv;
    }
}

// ---------------- active tile list + ticket reset ----------------------------
__global__ void k_tiles() {
    __shared__ int off[NEXP + 1];
    if (threadIdx.x == 0) {
        int t = 0;
        for (int e = 0; e < NEXP; e++) {
            off[e] = t;
            t += ((g_cnt[e] + 127) >> 7) * 16;
        }
        off[NEXP] = t;
        g_ntile  = t;
        g_ticket = 0;
    }
    __syncthreads();
    int total = off[NEXP];
    for (int s = threadIdx.x; s < total; s += blockDim.x) {
        int e = 0;
        while (s >= off[e + 1]) e++;
        int r  = s - off[e];
        int mt = r >> 4, nt = r & 15;
        g_tiles[s] = (e << 9) | (mt << 4) | nt;
    }
}

// ---------------- persistent gathered mma.sync tf32 GEMM ---------------------
// 296 persistent blocks (2/SM), 256 threads, 2-stage cp.async, 64x32 warp tile
#define BK 32
#define A_STR 36
#define B_STR 136
#define A_BYTES (128 * A_STR * 4)          // 18432
#define B_BYTES (BK * B_STR * 4)           // 17408
#define STAGE_BYTES (A_BYTES + B_BYTES)    // 35840
#define SMEM_TOTAL (2 * STAGE_BYTES)       // 71680 -> 2 CTAs/SM
#define NKC (DDIM / BK)                    // 64

__global__ void __launch_bounds__(256, 2) k_gemm(const float* __restrict__ be,
                                                 float* __restrict__ out) {
    extern __shared__ char smem[];
    __shared__ int s_tile;
    const uint32_t sb = smem_u32(smem);
    const int tid  = threadIdx.x;
    const int wid  = tid / 32, lane = tid % 32;
    const int g    = lane >> 2, t4 = lane & 3;
    const int wm   = (wid & 1) * 64;
    const int wn   = (wid >> 1) * 32;

    const int aRow  = tid >> 1;
    const int aColF = (tid & 1) * 16;
    const uint32_t aDst = sb + (uint32_t)(aRow * A_STR + aColF) * 4;
    const int bRow0 = tid >> 5;
    const int bColF = (tid & 31) * 4;
    const uint32_t bDst = sb + (uint32_t)A_BYTES + (uint32_t)(bRow0 * B_STR + bColF) * 4;

    for (;;) {
        CPA_WAIT0();                       // drain any in-flight stores to smem
        __syncthreads();
        if (tid == 0) {
            int s = atomicAdd(&g_ticket, 1);
            s_tile = (s < g_ntile) ? g_tiles[s] : -1;
        }
        __syncthreads();
        const int tl = s_tile;
        if (tl < 0) return;

        const int e  = tl >> 9;
        const int m0 = ((tl >> 4) & 31) * 128;
        const int n0 = (tl & 15) * 128;
        const int cnt = g_cnt[e];

        const int mIdx = min(m0 + aRow, cnt - 1);
        const float* aSrc = g_xr + (size_t)g_tok[e][mIdx] * DDIM + aColF;
        const float* bSrc = g_wr + (size_t)e * DDIM * HDIM + (size_t)bRow0 * HDIM + n0 + bColF;

        float acc[4][4][4];
#pragma unroll
        for (int i = 0; i < 4; i++)
#pragma unroll
            for (int j = 0; j < 4; j++)
#pragma unroll
                for (int c = 0; c < 4; c++) acc[i][j][c] = 0.f;

        auto load_tiles = [&](int kc, int st) {
            const uint32_t so = (uint32_t)(st * STAGE_BYTES);
            const float* ap = aSrc + kc * BK;
#pragma unroll
            for (int c = 0; c < 4; c++)
                CPA16(aDst + so + c * 16, ap + c * 4);
            const float* bp = bSrc + (size_t)(kc * BK) * HDIM;
#pragma unroll
            for (int p = 0; p < 4; p++)
                CPA16(bDst + so + (uint32_t)(p * 8 * B_STR) * 4,
                      bp + (size_t)(p * 8) * HDIM);
        };

        load_tiles(0, 0); CPA_COMMIT();
        load_tiles(1, 1); CPA_COMMIT();

        for (int kc = 0; kc < NKC; kc++) {
            const int st = kc & 1;
            CPA_WAIT1();
            __syncthreads();

            const uint32_t* As = reinterpret_cast<const uint32_t*>(smem + st * STAGE_BYTES);
            const uint32_t* Bs = reinterpret_cast<const uint32_t*>(smem + st * STAGE_BYTES + A_BYTES);

#pragma unroll
            for (int kk = 0; kk < 4; kk++) {
                const int k0 = kk * 8 + t4;
                uint32_t a[4][4], b[4][2];
#pragma unroll
                for (int i = 0; i < 4; i++) {
                    const uint32_t* ap = As + (wm + i * 16 + g) * A_STR + k0;
                    a[i][0] = ap[0];
                    a[i][2] = ap[4];
                    a[i][1] = ap[8 * A_STR];
                    a[i][3] = ap[8 * A_STR + 4];
                }
#pragma unroll
                for (int j = 0; j < 4; j++) {
                    const uint32_t* bp = Bs + k0 * B_STR + wn + j * 8 + g;
                    b[j][0] = bp[0];
                    b[j][1] = bp[4 * B_STR];
                }
#pragma unroll
                for (int i = 0; i < 4; i++)
#pragma unroll
                    for (int j = 0; j < 4; j++)
                        mma_tf32(acc[i][j], a[i], b[j]);
            }
            __syncthreads();

            if (kc + 2 < NKC) load_tiles(kc + 2, st);
            CPA_COMMIT();
        }

        // epilogue: out[b,n] += w * (acc + be[e,n])  (2 commutative fp32 adds/elem)
        const float* beRow = be + (size_t)e * HDIM + n0;
#pragma unroll
        for (int i = 0; i < 4; i++) {
#pragma unroll
            for (int half = 0; half < 2; half++) {
                const int m = m0 + wm + i * 16 + g + half * 8;
                if (m < cnt) {
                    const int   token = g_tok[e][m];
                    const float wgt   = g_w[e][m];
                    float* orow = out + (size_t)token * HDIM + n0;
#pragma unroll
                    for (int j = 0; j < 4; j++) {
                        const int n = wn + j * 8 + t4 * 2;
                        const float c0 = acc[i][j][half * 2 + 0];
                        const float c1 = acc[i][j][half * 2 + 1];
                        atomicAdd(&orow[n],     wgt * (c0 + beRow[n]));
                        atomicAdd(&orow[n + 1], wgt * (c1 + beRow[n + 1]));
                    }
                }
            }
        }
    }
}

// ---------------- launch ------------------------------------------------------
extern "C" void kernel_launch(void* const* d_in, const int* in_sizes, int n_in,
                              void* d_out, int out_size) {
    const float* x  = (const float*)d_in[0];
    const float* Wg = (const float*)d_in[1];
    const float* bg = (const float*)d_in[2];
    const float* We = (const float*)d_in[3];
    const float* be = (const float*)d_in[4];
    float* out = (float*)d_out;

    cudaFuncSetAttribute(k_gemm, cudaFuncAttributeMaxDynamicSharedMemorySize, SMEM_TOTAL);

    k_zero<<<8192, 256>>>((float4*)out);
    k_gate<<<BTOK / 8, dim3(32, 8)>>>(x, Wg, bg);

    // pre-round x and We to tf32 (rna) into static scratch
    float* xr = nullptr; float* wr = nullptr;
    cudaGetSymbolAddress((void**)&xr, g_xr);
    cudaGetSymbolAddress((void**)&wr, g_wr);
    {
        int n4x = (BTOK * DDIM) / 4;                       // 2,097,152
        k_round<<<(n4x + 255) / 256, 256>>>((const float4*)x, (float4*)xr, n4x);
        int n4w = (NEXP * DDIM * HDIM) / 4;                // 8,388,608
        k_round<<<(n4w + 255) / 256, 256>>>((const float4*)We, (float4*)wr, n4w);
    }

    k_tiles<<<1, 256>>>();
    k_gemm<<<296, 256, SMEM_TOTAL>>>(be, out);
}

// round 11
// speedup vs baseline: 1.0585x; 1.0585x over previous
#include <cuda_runtime.h>
#include <cstdint>

#define BTOK 4096
#define DDIM 2048
#define HDIM 2048
#define NEXP 8

// ---------------- static device scratch (allocations are forbidden) ----------
__device__ int   g_cnt[NEXP];
__device__ int   g_tok[NEXP][BTOK];
__device__ float g_w[NEXP][BTOK];
__device__ float g_xp[(size_t)BTOK * DDIM];   // rna(x), k-permuted in 8-blocks

// ---------------- helpers ----------------------------------------------------
__device__ __forceinline__ uint32_t smem_u32(const void* p) {
    uint32_t a;
    asm("{ .reg .u64 t; cvta.to.shared.u64 t, %1; cvt.u32.u64 %0, t; }" : "=r"(a) : "l"(p));
    return a;
}
__device__ __forceinline__ uint32_t f2tf32(float f) {
    uint32_t r; asm("cvt.rna.tf32.f32 %0, %1;" : "=r"(r) : "f"(f)); return r;
}
__device__ __forceinline__ float f2tf32f(float f) {
    uint32_t r; asm("cvt.rna.tf32.f32 %0, %1;" : "=r"(r) : "f"(f));
    return __uint_as_float(r);
}
#define CPA16(dst, src) \
    asm volatile("cp.async.cg.shared.global [%0], [%1], 16;" :: "r"(dst), "l"(src) : "memory")
#define CPA_COMMIT() asm volatile("cp.async.commit_group;" ::: "memory")
#define CPA_WAIT1()  asm volatile("cp.async.wait_group 1;" ::: "memory")

__device__ __forceinline__ void mma_tf32(float* c, const uint32_t* a, const uint32_t* b) {
    asm volatile(
        "mma.sync.aligned.m16n8k8.row.col.f32.tf32.tf32.f32 "
        "{%0,%1,%2,%3}, {%4,%5,%6,%7}, {%8,%9}, {%0,%1,%2,%3};"
        : "+f"(c[0]), "+f"(c[1]), "+f"(c[2]), "+f"(c[3])
        : "r"(a[0]), "r"(a[1]), "r"(a[2]), "r"(a[3]), "r"(b[0]), "r"(b[1]));
}

// ---------------- zero output + counters -------------------------------------
__global__ void k_zero(float4* __restrict__ out4) {
    long i = (long)blockIdx.x * blockDim.x + threadIdx.x;
    out4[i] = make_float4(0.f, 0.f, 0.f, 0.f);
    if (blockIdx.x == 0 && threadIdx.x < NEXP) g_cnt[threadIdx.x] = 0;
}

// ---------------- permute+round x: per 8-block k -> [0,4,1,5,2,6,3,7] --------
__global__ void k_permx(const float4* __restrict__ src, float4* __restrict__ dst, int n8) {
    int i = blockIdx.x * blockDim.x + threadIdx.x;   // one 8-float block per thread
    if (i < n8) {
        float4 v0 = src[i * 2];        // k 0..3
        float4 v1 = src[i * 2 + 1];    // k 4..7
        float4 o0, o1;
        o0.x = f2tf32f(v0.x); o0.y = f2tf32f(v1.x);  // 0,4
        o0.z = f2tf32f(v0.y); o0.w = f2tf32f(v1.y);  // 1,5
        o1.x = f2tf32f(v0.z); o1.y = f2tf32f(v1.z);  // 2,6
        o1.z = f2tf32f(v0.w); o1.w = f2tf32f(v1.w);  // 3,7
        dst[i * 2]     = o0;
        dst[i * 2 + 1] = o1;
    }
}

// ---------------- gating: softmax + top-2 routing (original x) ----------------
__global__ void k_gate(const float* __restrict__ x,
                       const float* __restrict__ Wg,
                       const float* __restrict__ bg) {
    int b    = blockIdx.x * 8 + threadIdx.y;
    int lane = threadIdx.x;
    const float* xr = x + (size_t)b * DDIM;
    float acc[NEXP];
#pragma unroll
    for (int e = 0; e < NEXP; e++) acc[e] = 0.f;
    for (int c = lane; c < DDIM; c += 32) {
        float xv = xr[c];
        const float4* w4 = reinterpret_cast<const float4*>(Wg + (size_t)c * NEXP);
        float4 w0 = w4[0], w1 = w4[1];
        acc[0] += xv * w0.x;  acc[1] += xv * w0.y;
        acc[2] += xv * w0.z;  acc[3] += xv * w0.w;
        acc[4] += xv * w1.x;  acc[5] += xv * w1.y;
        acc[6] += xv * w1.z;  acc[7] += xv * w1.w;
    }
#pragma unroll
    for (int off = 16; off > 0; off >>= 1)
#pragma unroll
        for (int e = 0; e < NEXP; e++)
            acc[e] += __shfl_xor_sync(0xFFFFFFFFu, acc[e], off);

    if (lane == 0) {
        float lg[NEXP], p[NEXP];
        float mx = -1e30f;
#pragma unroll
        for (int e = 0; e < NEXP; e++) { lg[e] = acc[e] + bg[e]; mx = fmaxf(mx, lg[e]); }
        float s = 0.f;
#pragma unroll
        for (int e = 0; e < NEXP; e++) { p[e] = expf(lg[e] - mx); s += p[e]; }
        float inv = 1.f / s;
        int i1 = 0;
#pragma unroll
        for (int e = 1; e < NEXP; e++) if (lg[e] > lg[i1]) i1 = e;
        int i2 = -1;
#pragma unroll
        for (int e = 0; e < NEXP; e++)
            if (e != i1 && (i2 < 0 || lg[e] > lg[i2])) i2 = e;
        int p1 = atomicAdd(&g_cnt[i1], 1);
        g_tok[i1][p1] = b;  g_w[i1][p1] = p[i1] * inv;
        int p2 = atomicAdd(&g_cnt[i2], 1);
        g_tok[i2][p2] = b;  g_w[i2][p2] = p[i2] * inv;
    }
}

// ---------------- gathered mma.sync tf32 GEMM (static grid, 2-stage) ---------
// grid (BTOK/128, HDIM/128, NEXP), 256 threads (8 warps, 2x4 warp grid, 64x32/warp)
#define BK 32
#define A_STR 36          // floats per A smem row -> LDS.64 banks (4g+2t4) conflict-free
#define B_STR 136         // floats per B smem row -> banks 8t4+g conflict-free
#define A_BYTES (128 * A_STR * 4)          // 18432
#define B_BYTES (BK * B_STR * 4)           // 17408
#define STAGE_BYTES (A_BYTES + B_BYTES)    // 35840
#define SMEM_TOTAL (2 * STAGE_BYTES)       // 71680 -> 2 CTAs/SM
#define NKC (DDIM / BK)                    // 64

__global__ void __launch_bounds__(256, 2) k_gemm(const float* __restrict__ We,
                                                 const float* __restrict__ be,
                                                 float* __restrict__ out) {
    const int e   = blockIdx.z;
    const int cnt = g_cnt[e];
    const int m0  = blockIdx.x * 128;
    if (m0 >= cnt) return;
    const int n0  = blockIdx.y * 128;

    extern __shared__ char smem[];
    const uint32_t sb = smem_u32(smem);
    const int tid  = threadIdx.x;
    const int wid  = tid / 32, lane = tid % 32;
    const int g    = lane >> 2, t4 = lane & 3;
    const int wm   = (wid & 1) * 64;
    const int wn   = (wid >> 1) * 32;

    // A: thread -> (row = tid/2, half = tid&1 covering 16 floats)
    const int aRow  = tid >> 1;
    const int aColF = (tid & 1) * 16;
    const int mIdx  = min(m0 + aRow, cnt - 1);
    const float* aSrc = g_xp + (size_t)g_tok[e][mIdx] * DDIM + aColF;
    const uint32_t aDst = sb + (uint32_t)(aRow * A_STR + aColF) * 4;
    // B: 4 passes; pass p: row = p*8 + tid/32, colf = (tid%32)*4
    const int bRow0 = tid >> 5;
    const int bColF = (tid & 31) * 4;
    const float* bSrc = We + (size_t)e * DDIM * HDIM + (size_t)bRow0 * HDIM + n0 + bColF;
    const uint32_t bDst = sb + (uint32_t)A_BYTES + (uint32_t)(bRow0 * B_STR + bColF) * 4;

    float acc[4][4][4];
#pragma unroll
    for (int i = 0; i < 4; i++)
#pragma unroll
        for (int j = 0; j < 4; j++)
#pragma unroll
            for (int c = 0; c < 4; c++) acc[i][j][c] = 0.f;

    auto load_tiles = [&](int kc, int st) {
        const uint32_t so = (uint32_t)(st * STAGE_BYTES);
        const float* ap = aSrc + kc * BK;
#pragma unroll
        for (int c = 0; c < 4; c++)
            CPA16(aDst + so + c * 16, ap + c * 4);
        const float* bp = bSrc + (size_t)(kc * BK) * HDIM;
#pragma unroll
        for (int p = 0; p < 4; p++)
            CPA16(bDst + so + (uint32_t)(p * 8 * B_STR) * 4,
                  bp + (size_t)(p * 8) * HDIM);
    };

    load_tiles(0, 0); CPA_COMMIT();
    load_tiles(1, 1); CPA_COMMIT();

    for (int kc = 0; kc < NKC; kc++) {
        const int st = kc & 1;
        CPA_WAIT1();
        __syncthreads();

        const uint32_t AsB = sb + (uint32_t)(st * STAGE_BYTES);
        const float* Bs = reinterpret_cast<const float*>(smem + st * STAGE_BYTES + A_BYTES);

#pragma unroll
        for (int kk = 0; kk < 4; kk++) {
            const int k0 = kk * 8 + t4;                 // B k-index (unpermuted)
            uint32_t a[4][4], b[4][2];
#pragma unroll
            for (int i = 0; i < 4; i++) {
                // permuted A: (k0, k0+4) are adjacent at float offset kk*8 + 2*t4
                const uint32_t aAddr = AsB +
                    (uint32_t)(((wm + i * 16 + g) * A_STR + kk * 8 + 2 * t4) * 4);
                asm volatile("ld.shared.v2.b32 {%0,%1}, [%2];"
                             : "=r"(a[i][0]), "=r"(a[i][2]) : "r"(aAddr));
                asm volatile("ld.shared.v2.b32 {%0,%1}, [%2];"
                             : "=r"(a[i][1]), "=r"(a[i][3])
                             : "r"(aAddr + (uint32_t)(8 * A_STR * 4)));
            }
#pragma unroll
            for (int j = 0; j < 4; j++) {
                const float* bp = Bs + k0 * B_STR + wn + j * 8 + g;
                b[j][0] = f2tf32(bp[0]);
                b[j][1] = f2tf32(bp[4 * B_STR]);
            }
#pragma unroll
            for (int i = 0; i < 4; i++)
#pragma unroll
                for (int j = 0; j < 4; j++)
                    mma_tf32(acc[i][j], a[i], b[j]);
        }
        __syncthreads();

        if (kc + 2 < NKC) load_tiles(kc + 2, st);
        CPA_COMMIT();
    }

    // epilogue: out[b,n] += w * (acc + be[e,n])  (2 commutative fp32 adds/elem)
    const float* beRow = be + (size_t)e * HDIM + n0;
#pragma unroll
    for (int i = 0; i < 4; i++) {
#pragma unroll
        for (int half = 0; half < 2; half++) {
            const int m = m0 + wm + i * 16 + g + half * 8;
            if (m < cnt) {
                const int   token = g_tok[e][m];
                const float wgt   = g_w[e][m];
                float* orow = out + (size_t)token * HDIM + n0;
#pragma unroll
                for (int j = 0; j < 4; j++) {
                    const int n = wn + j * 8 + t4 * 2;
                    const float c0 = acc[i][j][half * 2 + 0];
                    const float c1 = acc[i][j][half * 2 + 1];
                    atomicAdd(&orow[n],     wgt * (c0 + beRow[n]));
                    atomicAdd(&orow[n + 1], wgt * (c1 + beRow[n + 1]));
                }
            }
        }
    }
}

// ---------------- launch ------------------------------------------------------
extern "C" void kernel_launch(void* const* d_in, const int* in_sizes, int n_in,
                              void* d_out, int out_size) {
    const float* x  = (const float*)d_in[0];
    const float* Wg = (const float*)d_in[1];
    const float* bg = (const float*)d_in[2];
    const float* We = (const float*)d_in[3];
    const float* be = (const float*)d_in[4];
    float* out = (float*)d_out;

    cudaFuncSetAttribute(k_gemm, cudaFuncAttributeMaxDynamicSharedMemorySize, SMEM_TOTAL);

    k_zero<<<8192, 256>>>((float4*)out);
    k_gate<<<BTOK / 8, dim3(32, 8)>>>(x, Wg, bg);

    float* xp = nullptr;
    cudaGetSymbolAddress((void**)&xp, g_xp);
    {
        int n8 = (BTOK * DDIM) / 8;     // 1,048,576 8-float blocks
        k_permx<<<(n8 + 255) / 256, 256>>>((const float4*)x, (float4*)xp, n8);
    }

    dim3 grid(BTOK / 128, HDIM / 128, NEXP);
    k_gemm<<<grid, 256, SMEM_TOTAL>>>(We, be, out);
}